// round 15
// baseline (speedup 1.0000x reference)
#include <cuda_runtime.h>

#define N_NODES 50000
#define N_EDGES 800000
#define D 64
#define SCAN_B 256
#define SCAN_NBLK ((N_NODES + SCAN_B - 1) / SCAN_B)   // 196
#define MEAN_SPREAD 8
#define GEMM_SMEM (64 * 64 * 4 + 64 * 64 * 8)          // Ws 16KB + xsd 32KB = 48KB

// ---------------- scratch (static device memory; zero at load & at graph end)
__device__ float g_h [N_NODES * D];   // hs = (x @ W) * dinv[row]
__device__ float g_xa[N_NODES * D];   // ping
__device__ float g_xb[N_NODES * D];   // pong
__device__ float g_dinv[N_NODES];
__device__ int   g_cnt [N_NODES];     // in-degree histogram
__device__ int   g_cur [N_NODES];     // fill cursors
__device__ int   g_rowptr[N_NODES];   // block-local exclusive prefix
__device__ int   g_blocksum[SCAN_NBLK];
__device__ int   g_csr[N_EDGES];      // dst-sorted sources (norm factored out)
__device__ float g_meanacc[4 * MEAN_SPREAD * D];
__device__ int   g_scanctr;           // last-block-done counter (self-resetting)

__device__ __forceinline__ float* selbuf(int s) { return (s == 0) ? g_xa : g_xb; }

// packed fp32x2 FMA: d = a*b + d (elementwise, full fp32 precision)
__device__ __forceinline__ void fma2(unsigned long long& d,
                                     unsigned long long a,
                                     unsigned long long b) {
    asm("fma.rn.f32x2 %0, %1, %2, %3;" : "=l"(d) : "l"(a), "l"(b), "l"(d));
}

// int64 indices < 50000 have zero high words at odd int32 positions.
__device__ __forceinline__ int detect64(const int* __restrict__ p32) {
    return ((p32[1] | p32[3] | p32[5] | p32[7] |
             p32[9] | p32[11] | p32[13] | p32[15]) == 0);
}

__device__ __forceinline__ int load_idx(const void* ei, int pos, int is64) {
    int v = is64 ? (int)((const long long*)ei)[pos] : ((const int*)ei)[pos];
    return min(max(v, 0), N_NODES - 1);
}

// ---------------- in-degree histogram (reads raw edge buffer) ---------------
__global__ void k_hist(const void* __restrict__ ei) {
    __shared__ int s_is64;
    if (threadIdx.x == 0) s_is64 = detect64((const int*)ei);
    __syncthreads();
    int e = blockIdx.x * blockDim.x + threadIdx.x;
    if (e < N_EDGES) atomicAdd(&g_cnt[load_idx(ei, N_EDGES + e, s_is64)], 1);
}

// ---------------- scan (both stages fused; + dinv) ---------------------------
__global__ void k_scan() {
    __shared__ int sh[SCAN_B];
    __shared__ int isLast;
    int b = blockIdx.x, t = threadIdx.x;
    int i = b * SCAN_B + t;
    int v = (i < N_NODES) ? g_cnt[i] : 0;
    sh[t] = v;
    __syncthreads();
    for (int off = 1; off < SCAN_B; off <<= 1) {
        int add = (t >= off) ? sh[t - off] : 0;
        __syncthreads();
        sh[t] += add;
        __syncthreads();
    }
    if (i < N_NODES) {
        g_rowptr[i] = sh[t] - v;
        g_dinv[i]   = rsqrtf(1.0f + (float)v);
    }
    if (t == SCAN_B - 1) g_blocksum[b] = sh[t];
    __threadfence();
    if (t == 0) isLast = (atomicAdd(&g_scanctr, 1) == (int)gridDim.x - 1);
    __syncthreads();

    if (isLast) {
        int w = (t < SCAN_NBLK) ? g_blocksum[t] : 0;
        sh[t] = w;
        __syncthreads();
        for (int off = 1; off < SCAN_B; off <<= 1) {
            int add = (t >= off) ? sh[t - off] : 0;
            __syncthreads();
            sh[t] += add;
            __syncthreads();
        }
        if (t < SCAN_NBLK) g_blocksum[t] = sh[t] - w;
        if (t == 0) g_scanctr = 0;
    }
}

// ---------------- CSR fill: dst-sorted src only ------------------------------
__global__ void k_fill(const void* __restrict__ ei) {
    __shared__ int s_is64;
    if (threadIdx.x == 0) s_is64 = detect64((const int*)ei);
    __syncthreads();
    int e = blockIdx.x * blockDim.x + threadIdx.x;
    if (e >= N_EDGES) return;
    int s = load_idx(ei, e, s_is64);
    int d = load_idx(ei, N_EDGES + e, s_is64);
    int pos = g_rowptr[d] + g_blocksum[d >> 8] + atomicAdd(&g_cur[d], 1);
    g_csr[pos] = s;
}

// ---------------- GEMM: hs = (xin @ W) * dinv[row] ---------------------------
// 64 rows/block, 4x4 tile, packed f32x2 FMA. Activations pre-duplicated in
// smem so both FFMA2 operands come straight from LDS.128 (no pack/rotate).
// Per k4: 12 LDS.128 + 32 FFMA2 (vs 8 LDS + 64 FFMA scalar).
__global__ void __launch_bounds__(256, 2)
k_gemm(int in_sel, const float* __restrict__ x0, const float* __restrict__ W) {
    const float* xin = (in_sel < 0) ? x0 : (const float*)selbuf(in_sel);

    extern __shared__ float smem[];
    float*  Ws  = smem;                        // [64][64] floats, 16 KB
    float2* xsd = (float2*)(smem + 64 * 64);   // [64][64] duplicated, 32 KB

    int tid = threadIdx.x;
    const float4* W4 = (const float4*)W;
    float4* Ws4 = (float4*)Ws;
    #pragma unroll
    for (int i = tid; i < 1024; i += 256) Ws4[i] = W4[i];

    int row0 = blockIdx.x * 64;
    const float4* x4 = (const float4*)xin;
    #pragma unroll
    for (int i = tid; i < 1024; i += 256) {
        int r  = i >> 4;
        int kq = i & 15;
        int row = row0 + r;
        float4 v = (row < N_NODES) ? x4[row * 16 + kq]
                                   : make_float4(0.f, 0.f, 0.f, 0.f);
        float4* dst = (float4*)&xsd[r * 64 + kq * 4];
        dst[0] = make_float4(v.x, v.x, v.y, v.y);
        dst[1] = make_float4(v.z, v.z, v.w, v.w);
    }
    __syncthreads();

    int jc = (tid & 15) * 4;    // 4 output columns = 2 packed pairs
    int rc = (tid >> 4) * 4;    // 4 rows

    unsigned long long acc[4][2];
    #pragma unroll
    for (int r = 0; r < 4; r++) { acc[r][0] = 0ull; acc[r][1] = 0ull; }

    #pragma unroll
    for (int k4 = 0; k4 < 16; k4++) {
        // W pairs: natural lo/hi halves of a float4 row segment
        ulonglong2 wv[4];
        #pragma unroll
        for (int kk = 0; kk < 4; kk++)
            wv[kk] = *(const ulonglong2*)&Ws[(k4 * 4 + kk) * 64 + jc];
        // duplicated activations: {a_k,a_k},{a_k1,a_k1} per LDS.128
        ulonglong2 a01[4], a23[4];
        #pragma unroll
        for (int r = 0; r < 4; r++) {
            a01[r] = *(const ulonglong2*)&xsd[(rc + r) * 64 + k4 * 4];
            a23[r] = *(const ulonglong2*)&xsd[(rc + r) * 64 + k4 * 4 + 2];
        }
        #pragma unroll
        for (int r = 0; r < 4; r++) {
            fma2(acc[r][0], a01[r].x, wv[0].x);
            fma2(acc[r][1], a01[r].x, wv[0].y);
            fma2(acc[r][0], a01[r].y, wv[1].x);
            fma2(acc[r][1], a01[r].y, wv[1].y);
            fma2(acc[r][0], a23[r].x, wv[2].x);
            fma2(acc[r][1], a23[r].x, wv[2].y);
            fma2(acc[r][0], a23[r].y, wv[3].x);
            fma2(acc[r][1], a23[r].y, wv[3].y);
        }
    }

    #pragma unroll
    for (int r = 0; r < 4; r++) {
        int row = row0 + rc + r;
        if (row < N_NODES) {
            float di = g_dinv[row];
            float4 o;
            o.x = __uint_as_float((unsigned)(acc[r][0] & 0xffffffffu)) * di;
            o.y = __uint_as_float((unsigned)(acc[r][0] >> 32)) * di;
            o.z = __uint_as_float((unsigned)(acc[r][1] & 0xffffffffu)) * di;
            o.w = __uint_as_float((unsigned)(acc[r][1] >> 32)) * di;
            *(float4*)&g_h[row * 64 + jc] = o;
        }
    }
}

// ---------------- pull aggregation + fused mean (warp per node) --------------
__global__ void k_aggr(int out_sel, int layer, const float4* __restrict__ b4p) {
    int tid  = threadIdx.x;
    int warp = tid >> 5;
    int lane = tid & 31;
    int half = lane >> 4;
    int c4   = lane & 15;
    int node = blockIdx.x * 8 + warp;

    const float4* h4 = (const float4*)g_h;

    float4 acc = make_float4(0.f, 0.f, 0.f, 0.f);
    if (half == 0) acc = h4[node * 16 + c4];       // self-loop term hs[d]

    int beg = g_rowptr[node] + g_blocksum[node >> 8];
    int end = (node == N_NODES - 1)
                ? N_EDGES
                : (g_rowptr[node + 1] + g_blocksum[(node + 1) >> 8]);
    int len = end - beg;

    for (int j = half; j < len; j += 8) {
        int    s[4];
        float4 v[4];
        bool   p[4];
        #pragma unroll
        for (int u = 0; u < 4; u++) {
            int jj = j + 2 * u;
            p[u] = (jj < len);
            if (p[u]) s[u] = __ldg(&g_csr[beg + jj]);
        }
        #pragma unroll
        for (int u = 0; u < 4; u++)
            if (p[u]) v[u] = __ldg(&h4[s[u] * 16 + c4]);
        #pragma unroll
        for (int u = 0; u < 4; u++) {
            if (p[u]) {
                acc.x += v[u].x; acc.y += v[u].y;
                acc.z += v[u].z; acc.w += v[u].w;
            }
        }
    }

    acc.x += __shfl_down_sync(0xffffffffu, acc.x, 16);
    acc.y += __shfl_down_sync(0xffffffffu, acc.y, 16);
    acc.z += __shfl_down_sync(0xffffffffu, acc.z, 16);
    acc.w += __shfl_down_sync(0xffffffffu, acc.w, 16);

    __shared__ float4 sh4[8 * 16];
    if (half == 0) {
        float dd = g_dinv[node];
        float4 bv = __ldg(&b4p[c4]);
        float4 row;
        row.x = fmaf(acc.x, dd, bv.x);
        row.y = fmaf(acc.y, dd, bv.y);
        row.z = fmaf(acc.z, dd, bv.z);
        row.w = fmaf(acc.w, dd, bv.w);
        ((float4*)selbuf(out_sel))[node * 16 + c4] = row;
        sh4[warp * 16 + c4] = row;
    }
    __syncthreads();

    if (tid < 64) {
        const float* shf = (const float*)sh4;
        float s = 0.f;
        #pragma unroll
        for (int w = 0; w < 8; w++) s += shf[w * 64 + tid];
        atomicAdd(&g_meanacc[(layer * MEAN_SPREAD + (blockIdx.x & (MEAN_SPREAD - 1))) * D + tid], s);
    }
}

// ---------------- finish: write d_out; restore zero invariants --------------
__global__ void k_finish(float* __restrict__ out) {
    if (blockIdx.x == 0) {
        int t = threadIdx.x;
        int layer = t >> 6, c = t & 63;
        float s = 0.f;
        #pragma unroll
        for (int k = 0; k < MEAN_SPREAD; k++)
            s += g_meanacc[(layer * MEAN_SPREAD + k) * D + c];
        out[layer * D + c] = s * (1.0f / (float)N_NODES);
        __syncthreads();
        for (int i = t; i < 4 * MEAN_SPREAD * D; i += 256) g_meanacc[i] = 0.f;
    }
    int i = blockIdx.x * blockDim.x + threadIdx.x;
    if (i < N_NODES) { g_cnt[i] = 0; g_cur[i] = 0; }
}

// ---------------- launch ----------------
extern "C" void kernel_launch(void* const* d_in, const int* in_sizes, int n_in,
                              void* d_out, int out_size) {
    const float* x   = (const float*)d_in[0];
    const void*  ei  = d_in[1];
    float*       out = (float*)d_out;

    cudaFuncSetAttribute(k_gemm, cudaFuncAttributeMaxDynamicSharedMemorySize,
                         GEMM_SMEM);   // idempotent host state; capture-safe

    k_hist<<<(N_EDGES + 255) / 256, 256>>>(ei);
    k_scan<<<SCAN_NBLK, SCAN_B>>>();
    k_fill<<<(N_EDGES + 255) / 256, 256>>>(ei);

    for (int l = 0; l < 4; l++) {
        int in_sel  = (l == 0) ? -1 : ((l - 1) & 1);
        int out_sel = l & 1;
        const float* W = (const float*)d_in[2 + 2 * l];
        const float* b = (const float*)d_in[3 + 2 * l];
        k_gemm<<<(N_NODES + 63) / 64, 256, GEMM_SMEM>>>(in_sel, x, W);
        k_aggr<<<N_NODES / 8, 256>>>(out_sel, l, (const float4*)b);
    }
    k_finish<<<SCAN_NBLK, 256>>>(out);
}

// round 16
// speedup vs baseline: 1.0648x; 1.0648x over previous
#include <cuda_runtime.h>

#define N_NODES 50000
#define N_EDGES 800000
#define D 64
#define SCAN_B 256
#define SCAN_NBLK ((N_NODES + SCAN_B - 1) / SCAN_B)   // 196
#define MEAN_SPREAD 8
#define BUILD_GRID 256

// ---------------- scratch (static device memory; zero at load & at graph end)
__device__ float g_h [N_NODES * D];   // hs = (x @ W) * dinv[row]
__device__ float g_xa[N_NODES * D];   // ping
__device__ float g_xb[N_NODES * D];   // pong
__device__ float g_dinv[N_NODES];
__device__ int   g_cnt [N_NODES];     // in-degree histogram
__device__ int   g_cur [N_NODES];     // fill cursors
__device__ int   g_rowptr[N_NODES];   // block-local exclusive prefix
__device__ int   g_blocksum[SCAN_NBLK];
__device__ int   g_csr[N_EDGES];      // dst-sorted sources (norm factored out)
__device__ float g_meanacc[4 * MEAN_SPREAD * D];
__device__ int   g_bar;               // monotonic grid barrier (reset in k_finish)

__device__ __forceinline__ float* selbuf(int s) { return (s == 0) ? g_xa : g_xb; }

// int64 indices < 50000 have zero high words at odd int32 positions.
__device__ __forceinline__ int detect64(const int* __restrict__ p32) {
    return ((p32[1] | p32[3] | p32[5] | p32[7] |
             p32[9] | p32[11] | p32[13] | p32[15]) == 0);
}

__device__ __forceinline__ int load_idx(const void* ei, int pos, int is64) {
    int v = is64 ? (int)((const long long*)ei)[pos] : ((const int*)ei)[pos];
    return min(max(v, 0), N_NODES - 1);
}

// Monotonic software grid barrier. All BUILD_GRID blocks are resident
// (256 blocks << residency bound), so spinning is deadlock-free. The counter
// is never reset inside this kernel; k_finish restores it to 0.
__device__ __forceinline__ void gridbar(int phase) {
    __syncthreads();
    if (threadIdx.x == 0) {
        __threadfence();
        atomicAdd(&g_bar, 1);
        while (atomicAdd(&g_bar, 0) < phase * BUILD_GRID) {}
    }
    __syncthreads();
}

// ---------------- fused prologue: hist -> scan -> blocksum-scan -> fill ------
__global__ void __launch_bounds__(256, 2) k_build(const void* __restrict__ ei) {
    __shared__ int sh[SCAN_B];
    __shared__ int s_is64;
    int tid = threadIdx.x;
    int b   = blockIdx.x;
    if (tid == 0) s_is64 = detect64((const int*)ei);
    __syncthreads();
    int is64 = s_is64;

    // phase 1: in-degree histogram (strided over edges)
    for (int e = b * 256 + tid; e < N_EDGES; e += BUILD_GRID * 256)
        atomicAdd(&g_cnt[load_idx(ei, N_EDGES + e, is64)], 1);
    gridbar(1);

    // phase 2: per-tile exclusive scan + dinv (blocks 0..SCAN_NBLK-1)
    if (b < SCAN_NBLK) {
        int i = b * SCAN_B + tid;
        int v = (i < N_NODES) ? g_cnt[i] : 0;
        sh[tid] = v;
        __syncthreads();
        for (int off = 1; off < SCAN_B; off <<= 1) {
            int add = (tid >= off) ? sh[tid - off] : 0;
            __syncthreads();
            sh[tid] += add;
            __syncthreads();
        }
        if (i < N_NODES) {
            g_rowptr[i] = sh[tid] - v;               // block-local exclusive
            g_dinv[i]   = rsqrtf(1.0f + (float)v);   // +1 self-loop
        }
        if (tid == SCAN_B - 1) g_blocksum[b] = sh[tid];
    }
    gridbar(2);

    // phase 3: block 0 scans the block sums (196 <= 256)
    if (b == 0) {
        int w = (tid < SCAN_NBLK) ? g_blocksum[tid] : 0;
        sh[tid] = w;
        __syncthreads();
        for (int off = 1; off < SCAN_B; off <<= 1) {
            int add = (tid >= off) ? sh[tid - off] : 0;
            __syncthreads();
            sh[tid] += add;
            __syncthreads();
        }
        if (tid < SCAN_NBLK) g_blocksum[tid] = sh[tid] - w;   // exclusive
    }
    gridbar(3);

    // phase 4: CSR fill (strided over edges)
    for (int e = b * 256 + tid; e < N_EDGES; e += BUILD_GRID * 256) {
        int s = load_idx(ei, e, is64);
        int d = load_idx(ei, N_EDGES + e, is64);
        int pos = g_rowptr[d] + g_blocksum[d >> 8] + atomicAdd(&g_cur[d], 1);
        g_csr[pos] = s;
    }
}

// ---------------- GEMM: hs = (xin @ W) * dinv[row] ---------------------------
// 64 rows/block, 4x4 register tile, k4-chunk double-buffered in registers.
__global__ void __launch_bounds__(256, 2)
k_gemm(int in_sel, const float* __restrict__ x0, const float* __restrict__ W) {
    const float* xin = (in_sel < 0) ? x0 : (const float*)selbuf(in_sel);

    __shared__ float Ws[64 * 64];
    __shared__ float xs[64 * 64];

    int tid = threadIdx.x;
    const float4* W4 = (const float4*)W;
    float4* Ws4 = (float4*)Ws;
    #pragma unroll
    for (int i = tid; i < 1024; i += 256) Ws4[i] = W4[i];

    int row0 = blockIdx.x * 64;
    const float4* x4 = (const float4*)xin;
    float4* xs4 = (float4*)xs;
    #pragma unroll
    for (int i = tid; i < 1024; i += 256) {
        int r = row0 + (i >> 4);
        xs4[i] = (r < N_NODES) ? x4[r * 16 + (i & 15)]
                               : make_float4(0.f, 0.f, 0.f, 0.f);
    }
    __syncthreads();

    int jc = (tid & 15) * 4;    // 4 output columns
    int rc = (tid >> 4) * 4;    // 4 rows

    float4 acc[4];
    #pragma unroll
    for (int r = 0; r < 4; r++) acc[r] = make_float4(0.f, 0.f, 0.f, 0.f);

    float4 wv[4], av[4], wn[4], an[4];
    #pragma unroll
    for (int kk = 0; kk < 4; kk++)
        wv[kk] = *(const float4*)&Ws[kk * 64 + jc];
    #pragma unroll
    for (int r = 0; r < 4; r++)
        av[r] = *(const float4*)&xs[(rc + r) * 64];

    #pragma unroll
    for (int k4 = 0; k4 < 16; k4++) {
        if (k4 < 15) {   // prefetch next chunk while FMAs below execute
            #pragma unroll
            for (int kk = 0; kk < 4; kk++)
                wn[kk] = *(const float4*)&Ws[((k4 + 1) * 4 + kk) * 64 + jc];
            #pragma unroll
            for (int r = 0; r < 4; r++)
                an[r] = *(const float4*)&xs[(rc + r) * 64 + (k4 + 1) * 4];
        }
        #pragma unroll
        for (int r = 0; r < 4; r++) {
            float4 a = av[r];
            acc[r].x = fmaf(a.x, wv[0].x, acc[r].x);
            acc[r].y = fmaf(a.x, wv[0].y, acc[r].y);
            acc[r].z = fmaf(a.x, wv[0].z, acc[r].z);
            acc[r].w = fmaf(a.x, wv[0].w, acc[r].w);
            acc[r].x = fmaf(a.y, wv[1].x, acc[r].x);
            acc[r].y = fmaf(a.y, wv[1].y, acc[r].y);
            acc[r].z = fmaf(a.y, wv[1].z, acc[r].z);
            acc[r].w = fmaf(a.y, wv[1].w, acc[r].w);
            acc[r].x = fmaf(a.z, wv[2].x, acc[r].x);
            acc[r].y = fmaf(a.z, wv[2].y, acc[r].y);
            acc[r].z = fmaf(a.z, wv[2].z, acc[r].z);
            acc[r].w = fmaf(a.z, wv[2].w, acc[r].w);
            acc[r].x = fmaf(a.w, wv[3].x, acc[r].x);
            acc[r].y = fmaf(a.w, wv[3].y, acc[r].y);
            acc[r].z = fmaf(a.w, wv[3].z, acc[r].z);
            acc[r].w = fmaf(a.w, wv[3].w, acc[r].w);
        }
        #pragma unroll
        for (int kk = 0; kk < 4; kk++) wv[kk] = wn[kk];
        #pragma unroll
        for (int r = 0; r < 4; r++) av[r] = an[r];
    }

    #pragma unroll
    for (int r = 0; r < 4; r++) {
        int row = row0 + rc + r;
        if (row < N_NODES) {
            float di = g_dinv[row];
            float4 o = acc[r];
            o.x *= di; o.y *= di; o.z *= di; o.w *= di;
            *(float4*)&g_h[row * 64 + jc] = o;
        }
    }
}

// ---------------- pull aggregation + fused mean (warp per node) --------------
__global__ void k_aggr(int out_sel, int layer, const float4* __restrict__ b4p) {
    int tid  = threadIdx.x;
    int warp = tid >> 5;
    int lane = tid & 31;
    int half = lane >> 4;
    int c4   = lane & 15;
    int node = blockIdx.x * 8 + warp;

    const float4* h4 = (const float4*)g_h;

    float4 acc = make_float4(0.f, 0.f, 0.f, 0.f);
    if (half == 0) acc = h4[node * 16 + c4];       // self-loop term hs[d]

    int beg = g_rowptr[node] + g_blocksum[node >> 8];
    int end = (node == N_NODES - 1)
                ? N_EDGES
                : (g_rowptr[node + 1] + g_blocksum[(node + 1) >> 8]);
    int len = end - beg;

    for (int j = half; j < len; j += 8) {
        int    s[4];
        float4 v[4];
        bool   p[4];
        #pragma unroll
        for (int u = 0; u < 4; u++) {
            int jj = j + 2 * u;
            p[u] = (jj < len);
            if (p[u]) s[u] = __ldg(&g_csr[beg + jj]);
        }
        #pragma unroll
        for (int u = 0; u < 4; u++)
            if (p[u]) v[u] = __ldg(&h4[s[u] * 16 + c4]);
        #pragma unroll
        for (int u = 0; u < 4; u++) {
            if (p[u]) {
                acc.x += v[u].x; acc.y += v[u].y;
                acc.z += v[u].z; acc.w += v[u].w;
            }
        }
    }

    acc.x += __shfl_down_sync(0xffffffffu, acc.x, 16);
    acc.y += __shfl_down_sync(0xffffffffu, acc.y, 16);
    acc.z += __shfl_down_sync(0xffffffffu, acc.z, 16);
    acc.w += __shfl_down_sync(0xffffffffu, acc.w, 16);

    __shared__ float4 sh4[8 * 16];
    if (half == 0) {
        float dd = g_dinv[node];
        float4 bv = __ldg(&b4p[c4]);
        float4 row;
        row.x = fmaf(acc.x, dd, bv.x);
        row.y = fmaf(acc.y, dd, bv.y);
        row.z = fmaf(acc.z, dd, bv.z);
        row.w = fmaf(acc.w, dd, bv.w);
        ((float4*)selbuf(out_sel))[node * 16 + c4] = row;
        sh4[warp * 16 + c4] = row;
    }
    __syncthreads();

    if (tid < 64) {
        const float* shf = (const float*)sh4;
        float s = 0.f;
        #pragma unroll
        for (int w = 0; w < 8; w++) s += shf[w * 64 + tid];
        atomicAdd(&g_meanacc[(layer * MEAN_SPREAD + (blockIdx.x & (MEAN_SPREAD - 1))) * D + tid], s);
    }
}

// ---------------- finish: write d_out; restore zero invariants --------------
__global__ void k_finish(float* __restrict__ out) {
    if (blockIdx.x == 0) {
        int t = threadIdx.x;
        int layer = t >> 6, c = t & 63;
        float s = 0.f;
        #pragma unroll
        for (int k = 0; k < MEAN_SPREAD; k++)
            s += g_meanacc[(layer * MEAN_SPREAD + k) * D + c];
        out[layer * D + c] = s * (1.0f / (float)N_NODES);
        __syncthreads();
        for (int i = t; i < 4 * MEAN_SPREAD * D; i += 256) g_meanacc[i] = 0.f;
        if (t == 0) g_bar = 0;                       // reset grid barrier
    }
    int i = blockIdx.x * blockDim.x + threadIdx.x;
    if (i < N_NODES) { g_cnt[i] = 0; g_cur[i] = 0; }
}

// ---------------- launch ----------------
extern "C" void kernel_launch(void* const* d_in, const int* in_sizes, int n_in,
                              void* d_out, int out_size) {
    const float* x   = (const float*)d_in[0];
    const void*  ei  = d_in[1];
    float*       out = (float*)d_out;

    k_build<<<BUILD_GRID, 256>>>(ei);

    for (int l = 0; l < 4; l++) {
        int in_sel  = (l == 0) ? -1 : ((l - 1) & 1);
        int out_sel = l & 1;
        const float* W = (const float*)d_in[2 + 2 * l];
        const float* b = (const float*)d_in[3 + 2 * l];
        k_gemm<<<(N_NODES + 63) / 64, 256>>>(in_sel, x, W);
        k_aggr<<<N_NODES / 8, 256>>>(out_sel, l, (const float4*)b);
    }
    k_finish<<<SCAN_NBLK, 256>>>(out);
}

// round 17
// speedup vs baseline: 1.0993x; 1.0324x over previous
#include <cuda_runtime.h>

#define N_NODES 50000
#define N_EDGES 800000
#define D 64
#define SCAN_B 256
#define SCAN_NBLK ((N_NODES + SCAN_B - 1) / SCAN_B)   // 196
#define MEAN_SPREAD 8

// ---------------- scratch (static device memory; zero at load & at graph end)
__device__ float g_h [N_NODES * D];   // hs = (x @ W) * dinv[row]
__device__ float g_xa[N_NODES * D];   // ping
__device__ float g_xb[N_NODES * D];   // pong
__device__ float g_dinv[N_NODES];
__device__ int   g_cnt [N_NODES];     // in-degree histogram
__device__ int   g_cur [N_NODES];     // fill cursors
__device__ int   g_rowptr[N_NODES];   // block-local exclusive prefix
__device__ int   g_blocksum[SCAN_NBLK];
__device__ int   g_csr[N_EDGES];      // dst-sorted sources (norm factored out)
__device__ float g_meanacc[4 * MEAN_SPREAD * D];
__device__ int   g_scanctr;           // last-block-done counter (self-resetting)

__device__ __forceinline__ float* selbuf(int s) { return (s == 0) ? g_xa : g_xb; }

// int64 indices < 50000 have zero high words at odd int32 positions.
__device__ __forceinline__ int detect64(const int* __restrict__ p32) {
    return ((p32[1] | p32[3] | p32[5] | p32[7] |
             p32[9] | p32[11] | p32[13] | p32[15]) == 0);
}

__device__ __forceinline__ int load_idx(const void* ei, int pos, int is64) {
    int v = is64 ? (int)((const long long*)ei)[pos] : ((const int*)ei)[pos];
    return min(max(v, 0), N_NODES - 1);
}

// ---------------- in-degree histogram (reads raw edge buffer) ---------------
__global__ void k_hist(const void* __restrict__ ei) {
    __shared__ int s_is64;
    if (threadIdx.x == 0) s_is64 = detect64((const int*)ei);
    __syncthreads();
    int e = blockIdx.x * blockDim.x + threadIdx.x;
    if (e < N_EDGES) atomicAdd(&g_cnt[load_idx(ei, N_EDGES + e, s_is64)], 1);
}

// ---------------- scan (both stages fused; + dinv) ---------------------------
__global__ void k_scan() {
    __shared__ int sh[SCAN_B];
    __shared__ int isLast;
    int b = blockIdx.x, t = threadIdx.x;
    int i = b * SCAN_B + t;
    int v = (i < N_NODES) ? g_cnt[i] : 0;
    sh[t] = v;
    __syncthreads();
    for (int off = 1; off < SCAN_B; off <<= 1) {
        int add = (t >= off) ? sh[t - off] : 0;
        __syncthreads();
        sh[t] += add;
        __syncthreads();
    }
    if (i < N_NODES) {
        g_rowptr[i] = sh[t] - v;
        g_dinv[i]   = rsqrtf(1.0f + (float)v);
    }
    if (t == SCAN_B - 1) g_blocksum[b] = sh[t];
    __threadfence();
    if (t == 0) isLast = (atomicAdd(&g_scanctr, 1) == (int)gridDim.x - 1);
    __syncthreads();

    if (isLast) {
        int w = (t < SCAN_NBLK) ? g_blocksum[t] : 0;
        sh[t] = w;
        __syncthreads();
        for (int off = 1; off < SCAN_B; off <<= 1) {
            int add = (t >= off) ? sh[t - off] : 0;
            __syncthreads();
            sh[t] += add;
            __syncthreads();
        }
        if (t < SCAN_NBLK) g_blocksum[t] = sh[t] - w;
        if (t == 0) g_scanctr = 0;
    }
}

// ---------------- CSR fill: dst-sorted src only ------------------------------
__global__ void k_fill(const void* __restrict__ ei) {
    __shared__ int s_is64;
    if (threadIdx.x == 0) s_is64 = detect64((const int*)ei);
    __syncthreads();
    int e = blockIdx.x * blockDim.x + threadIdx.x;
    if (e >= N_EDGES) return;
    int s = load_idx(ei, e, s_is64);
    int d = load_idx(ei, N_EDGES + e, s_is64);
    int pos = g_rowptr[d] + g_blocksum[d >> 8] + atomicAdd(&g_cur[d], 1);
    g_csr[pos] = s;
}

// ---------------- GEMM: hs = (xin @ W) * dinv[row] ---------------------------
// 64 rows/block, 4x4 register tile. Half pipeline: W chunk prefetched in
// registers (wn), A chunk loaded just-in-time; ~76 live regs -> 3 blocks/SM.
__global__ void __launch_bounds__(256, 3)
k_gemm(int in_sel, const float* __restrict__ x0, const float* __restrict__ W) {
    const float* xin = (in_sel < 0) ? x0 : (const float*)selbuf(in_sel);

    __shared__ float Ws[64 * 64];
    __shared__ float xs[64 * 64];

    int tid = threadIdx.x;
    const float4* W4 = (const float4*)W;
    float4* Ws4 = (float4*)Ws;
    #pragma unroll
    for (int i = tid; i < 1024; i += 256) Ws4[i] = W4[i];

    int row0 = blockIdx.x * 64;
    const float4* x4 = (const float4*)xin;
    float4* xs4 = (float4*)xs;
    #pragma unroll
    for (int i = tid; i < 1024; i += 256) {
        int r = row0 + (i >> 4);
        xs4[i] = (r < N_NODES) ? x4[r * 16 + (i & 15)]
                               : make_float4(0.f, 0.f, 0.f, 0.f);
    }
    __syncthreads();

    int jc = (tid & 15) * 4;    // 4 output columns
    int rc = (tid >> 4) * 4;    // 4 rows

    float4 acc[4];
    #pragma unroll
    for (int r = 0; r < 4; r++) acc[r] = make_float4(0.f, 0.f, 0.f, 0.f);

    float4 wv[4], wn[4];
    #pragma unroll
    for (int kk = 0; kk < 4; kk++)
        wv[kk] = *(const float4*)&Ws[kk * 64 + jc];

    #pragma unroll
    for (int k4 = 0; k4 < 16; k4++) {
        if (k4 < 15) {   // prefetch next W chunk while FMAs below execute
            #pragma unroll
            for (int kk = 0; kk < 4; kk++)
                wn[kk] = *(const float4*)&Ws[((k4 + 1) * 4 + kk) * 64 + jc];
        }
        #pragma unroll
        for (int r = 0; r < 4; r++) {
            float4 a = *(const float4*)&xs[(rc + r) * 64 + k4 * 4];  // JIT load
            acc[r].x = fmaf(a.x, wv[0].x, acc[r].x);
            acc[r].y = fmaf(a.x, wv[0].y, acc[r].y);
            acc[r].z = fmaf(a.x, wv[0].z, acc[r].z);
            acc[r].w = fmaf(a.x, wv[0].w, acc[r].w);
            acc[r].x = fmaf(a.y, wv[1].x, acc[r].x);
            acc[r].y = fmaf(a.y, wv[1].y, acc[r].y);
            acc[r].z = fmaf(a.y, wv[1].z, acc[r].z);
            acc[r].w = fmaf(a.y, wv[1].w, acc[r].w);
            acc[r].x = fmaf(a.z, wv[2].x, acc[r].x);
            acc[r].y = fmaf(a.z, wv[2].y, acc[r].y);
            acc[r].z = fmaf(a.z, wv[2].z, acc[r].z);
            acc[r].w = fmaf(a.z, wv[2].w, acc[r].w);
            acc[r].x = fmaf(a.w, wv[3].x, acc[r].x);
            acc[r].y = fmaf(a.w, wv[3].y, acc[r].y);
            acc[r].z = fmaf(a.w, wv[3].z, acc[r].z);
            acc[r].w = fmaf(a.w, wv[3].w, acc[r].w);
        }
        #pragma unroll
        for (int kk = 0; kk < 4; kk++) wv[kk] = wn[kk];
    }

    #pragma unroll
    for (int r = 0; r < 4; r++) {
        int row = row0 + rc + r;
        if (row < N_NODES) {
            float di = g_dinv[row];
            float4 o = acc[r];
            o.x *= di; o.y *= di; o.z *= di; o.w *= di;
            *(float4*)&g_h[row * 64 + jc] = o;
        }
    }
}

// ---------------- pull aggregation + fused mean (warp per node) --------------
__global__ void k_aggr(int out_sel, int layer, const float4* __restrict__ b4p) {
    int tid  = threadIdx.x;
    int warp = tid >> 5;
    int lane = tid & 31;
    int half = lane >> 4;
    int c4   = lane & 15;
    int node = blockIdx.x * 8 + warp;

    const float4* h4 = (const float4*)g_h;

    float4 acc = make_float4(0.f, 0.f, 0.f, 0.f);
    if (half == 0) acc = h4[node * 16 + c4];       // self-loop term hs[d]

    int beg = g_rowptr[node] + g_blocksum[node >> 8];
    int end = (node == N_NODES - 1)
                ? N_EDGES
                : (g_rowptr[node + 1] + g_blocksum[(node + 1) >> 8]);
    int len = end - beg;

    for (int j = half; j < len; j += 8) {
        int    s[4];
        float4 v[4];
        bool   p[4];
        #pragma unroll
        for (int u = 0; u < 4; u++) {
            int jj = j + 2 * u;
            p[u] = (jj < len);
            if (p[u]) s[u] = __ldg(&g_csr[beg + jj]);
        }
        #pragma unroll
        for (int u = 0; u < 4; u++)
            if (p[u]) v[u] = __ldg(&h4[s[u] * 16 + c4]);
        #pragma unroll
        for (int u = 0; u < 4; u++) {
            if (p[u]) {
                acc.x += v[u].x; acc.y += v[u].y;
                acc.z += v[u].z; acc.w += v[u].w;
            }
        }
    }

    acc.x += __shfl_down_sync(0xffffffffu, acc.x, 16);
    acc.y += __shfl_down_sync(0xffffffffu, acc.y, 16);
    acc.z += __shfl_down_sync(0xffffffffu, acc.z, 16);
    acc.w += __shfl_down_sync(0xffffffffu, acc.w, 16);

    __shared__ float4 sh4[8 * 16];
    if (half == 0) {
        float dd = g_dinv[node];
        float4 bv = __ldg(&b4p[c4]);
        float4 row;
        row.x = fmaf(acc.x, dd, bv.x);
        row.y = fmaf(acc.y, dd, bv.y);
        row.z = fmaf(acc.z, dd, bv.z);
        row.w = fmaf(acc.w, dd, bv.w);
        ((float4*)selbuf(out_sel))[node * 16 + c4] = row;
        sh4[warp * 16 + c4] = row;
    }
    __syncthreads();

    if (tid < 64) {
        const float* shf = (const float*)sh4;
        float s = 0.f;
        #pragma unroll
        for (int w = 0; w < 8; w++) s += shf[w * 64 + tid];
        atomicAdd(&g_meanacc[(layer * MEAN_SPREAD + (blockIdx.x & (MEAN_SPREAD - 1))) * D + tid], s);
    }
}

// ---------------- finish: write d_out; restore zero invariants --------------
__global__ void k_finish(float* __restrict__ out) {
    if (blockIdx.x == 0) {
        int t = threadIdx.x;
        int layer = t >> 6, c = t & 63;
        float s = 0.f;
        #pragma unroll
        for (int k = 0; k < MEAN_SPREAD; k++)
            s += g_meanacc[(layer * MEAN_SPREAD + k) * D + c];
        out[layer * D + c] = s * (1.0f / (float)N_NODES);
        __syncthreads();
        for (int i = t; i < 4 * MEAN_SPREAD * D; i += 256) g_meanacc[i] = 0.f;
    }
    int i = blockIdx.x * blockDim.x + threadIdx.x;
    if (i < N_NODES) { g_cnt[i] = 0; g_cur[i] = 0; }
}

// ---------------- launch ----------------
extern "C" void kernel_launch(void* const* d_in, const int* in_sizes, int n_in,
                              void* d_out, int out_size) {
    const float* x   = (const float*)d_in[0];
    const void*  ei  = d_in[1];
    float*       out = (float*)d_out;

    k_hist<<<(N_EDGES + 255) / 256, 256>>>(ei);
    k_scan<<<SCAN_NBLK, SCAN_B>>>();
    k_fill<<<(N_EDGES + 255) / 256, 256>>>(ei);

    for (int l = 0; l < 4; l++) {
        int in_sel  = (l == 0) ? -1 : ((l - 1) & 1);
        int out_sel = l & 1;
        const float* W = (const float*)d_in[2 + 2 * l];
        const float* b = (const float*)d_in[3 + 2 * l];
        k_gemm<<<(N_NODES + 63) / 64, 256>>>(in_sel, x, W);
        k_aggr<<<N_NODES / 8, 256>>>(out_sel, l, (const float4*)b);
    }
    k_finish<<<SCAN_NBLK, 256>>>(out);
}